// round 6
// baseline (speedup 1.0000x reference)
#include <cuda_runtime.h>

#define N_ENT  100000
#define N_EDGE 1600000
#define N_REL  64

// Scratch (allocation-free rule: __device__ globals)
static __device__ float g_tailproj[N_ENT * 64];    // W_t · emb[n]
static __device__ float g_headrec [N_ENT * 128];   // [W_h·emb | M_h·emb]
static __device__ float g_self    [N_ENT * 128];   // [W_r·self_rel + b | M_r·self_rel]
static __device__ float g_selfrel [N_ENT * 32];    // mean incoming rel embedding
static __device__ float g_arel    [N_REL * 64];    // W_r·emb_rel[r] + attn_b
static __device__ float g_mrel    [N_REL * 64];    // M_r·emb_rel[r]
static __device__ int   g_hist    [N_ENT * 64];    // per-node relation histogram
static __device__ int   g_deg     [N_ENT];         // in-degree (excl. self)
static __device__ int   g_off     [N_ENT + 1];     // CSR offsets
static __device__ int   g_cursor  [N_ENT];         // scatter cursors
static __device__ int2  g_sorted  [N_EDGE];        // (head | rel<<17, tail) by tail
static __device__ float g_sum     [N_ENT * 8];     // softmax denominators (real edges)
static __device__ float g_acc     [N_ENT * 64];    // unnormalized accum (real edges)

typedef unsigned long long u64;

__device__ __forceinline__ u64 pack2(float lo, float hi) {
    u64 r;
    asm("mov.b64 %0, {%1, %2};" : "=l"(r) : "f"(lo), "f"(hi));
    return r;
}
__device__ __forceinline__ void unpack2(u64 v, float& lo, float& hi) {
    asm("mov.b64 {%0, %1}, %2;" : "=f"(lo), "=f"(hi) : "l"(v));
}
__device__ __forceinline__ u64 fma2(u64 a, u64 b, u64 c) {
    u64 d;
    asm("fma.rn.f32x2 %0, %1, %2, %3;" : "=l"(d) : "l"(a), "l"(b), "l"(c));
    return d;
}

// ---------------------------------------------------------------------------
__global__ void rel_tables_kernel(const float* __restrict__ emb_rel,
                                  const float* __restrict__ attn_W,
                                  const float* __restrict__ attn_b,
                                  const float* __restrict__ aggr_W) {
    int r = threadIdx.x;
    if (r >= N_REL) return;
    float ev[32];
#pragma unroll
    for (int k = 0; k < 32; k++) ev[k] = emb_rel[r * 32 + k];
    for (int o = 0; o < 64; o++) {
        float a = attn_b[o], m = 0.f;
#pragma unroll
        for (int k = 0; k < 32; k++) {
            a = fmaf(attn_W[o * 96 + 64 + k], ev[k], a);
            m = fmaf(aggr_W[o * 64 + 32 + k], ev[k], m);
        }
        g_arel[r * 64 + o] = a;
        g_mrel[r * 64 + o] = m;
    }
}

// ---------------------------------------------------------------------------
__global__ void hist_kernel(const int* __restrict__ tail,
                            const int* __restrict__ rel) {
    int e = blockIdx.x * blockDim.x + threadIdx.x;
    if (e < N_EDGE) atomicAdd(&g_hist[tail[e] * 64 + rel[e]], 1);
}

// ---------------------------------------------------------------------------
// Mean incoming rel embedding per node (32-dim) + degree: one warp per node.
__global__ void selfrel_kernel(const float* __restrict__ emb_rel) {
    __shared__ float s_rel[N_REL * 32];   // 8KB
    for (int i = threadIdx.x; i < N_REL * 32; i += blockDim.x)
        s_rel[i] = emb_rel[i];
    __syncthreads();
    int lane = threadIdx.x & 31;
    int n = blockIdx.x * (blockDim.x >> 5) + (threadIdx.x >> 5);
    if (n >= N_ENT) return;
    int h0 = g_hist[n * 64 + lane];
    int h1 = g_hist[n * 64 + 32 + lane];
    unsigned tot = __reduce_add_sync(0xffffffffu, (unsigned)(h0 + h1));
    if (lane == 0) g_deg[n] = (int)tot;
    float inv = 1.f / (float)tot;
    float acc = 0.f;
#pragma unroll
    for (int r = 0; r < 64; r++) {
        int hr = (r < 32) ? __shfl_sync(0xffffffffu, h0, r)
                          : __shfl_sync(0xffffffffu, h1, r - 32);
        if (hr) acc = fmaf((float)hr, s_rel[r * 32 + lane], acc);
    }
    g_selfrel[n * 32 + lane] = acc * inv;
}

// ---------------------------------------------------------------------------
// Exclusive prefix sum over degrees: single block, 1024 threads
__global__ void scan_kernel() {
    __shared__ int s[1024];
    const int T = 1024, C = (N_ENT + T - 1) / T;
    int tid = threadIdx.x;
    int base = tid * C;
    int sum = 0;
    for (int i = 0; i < C; i++) {
        int n = base + i;
        if (n < N_ENT) sum += g_deg[n];
    }
    s[tid] = sum;
    __syncthreads();
    for (int d = 1; d < T; d <<= 1) {
        int v = (tid >= d) ? s[tid - d] : 0;
        __syncthreads();
        s[tid] += v;
        __syncthreads();
    }
    int run = tid ? s[tid - 1] : 0;
    for (int i = 0; i < C; i++) {
        int n = base + i;
        if (n < N_ENT) {
            g_off[n] = run;
            g_cursor[n] = run;
            run += g_deg[n];
        }
    }
    if (tid == T - 1) g_off[N_ENT] = run;
}

// ---------------------------------------------------------------------------
__global__ void scatter_kernel(const int* __restrict__ head,
                               const int* __restrict__ tail,
                               const int* __restrict__ rel) {
    int e = blockIdx.x * blockDim.x + threadIdx.x;
    if (e >= N_EDGE) return;
    int tn = tail[e];
    int pos = atomicAdd(&g_cursor[tn], 1);
    g_sorted[pos] = make_int2(head[e] | (rel[e] << 17), tn);
}

// ---------------------------------------------------------------------------
// Per-node projections (5 GEMVs fused): 4 nodes per warp per k-step, weights
// packed as (o=lane, o=lane+32) float2 pairs -> LDS.64 + fma.rn.f32x2.
__global__ void __launch_bounds__(256) node_proj_kernel(
        const float* __restrict__ emb_ent,
        const float* __restrict__ attn_W,
        const float* __restrict__ attn_b,
        const float* __restrict__ aggr_W) {
    __shared__ float2 s_w[5][32 * 32];
    for (int i = threadIdx.x; i < 1024; i += blockDim.x) {
        int k = i >> 5, l = i & 31;
        s_w[0][i] = make_float2(attn_W[l * 96 + k],      attn_W[(l + 32) * 96 + k]);
        s_w[1][i] = make_float2(attn_W[l * 96 + 32 + k], attn_W[(l + 32) * 96 + 32 + k]);
        s_w[2][i] = make_float2(attn_W[l * 96 + 64 + k], attn_W[(l + 32) * 96 + 64 + k]);
        s_w[3][i] = make_float2(aggr_W[l * 64 + k],      aggr_W[(l + 32) * 64 + k]);
        s_w[4][i] = make_float2(aggr_W[l * 64 + 32 + k], aggr_W[(l + 32) * 64 + 32 + k]);
    }
    __syncthreads();

    int lane = threadIdx.x & 31;
    int gw   = blockIdx.x * (blockDim.x >> 5) + (threadIdx.x >> 5);
    int GW   = gridDim.x * (blockDim.x >> 5);
    u64 bias = pack2(attn_b[lane], attn_b[32 + lane]);

    for (int base = gw * 4; base < N_ENT; base += GW * 4) {   // N_ENT % 4 == 0
        float e0 = emb_ent[(base + 0) * 32 + lane];
        float e1 = emb_ent[(base + 1) * 32 + lane];
        float e2 = emb_ent[(base + 2) * 32 + lane];
        float e3 = emb_ent[(base + 3) * 32 + lane];
        float r0 = g_selfrel[(base + 0) * 32 + lane];
        float r1 = g_selfrel[(base + 1) * 32 + lane];
        float r2 = g_selfrel[(base + 2) * 32 + lane];
        float r3 = g_selfrel[(base + 3) * 32 + lane];

        u64 A[4], B[4], C[4], M[4], D[4];
#pragma unroll
        for (int i = 0; i < 4; i++) { A[i] = 0; B[i] = 0; C[i] = bias; M[i] = 0; D[i] = 0; }

#pragma unroll
        for (int k = 0; k < 32; k++) {
            u64 w0 = *(const u64*)&s_w[0][k * 32 + lane];
            u64 w1 = *(const u64*)&s_w[1][k * 32 + lane];
            u64 w2 = *(const u64*)&s_w[2][k * 32 + lane];
            u64 w3 = *(const u64*)&s_w[3][k * 32 + lane];
            u64 w4 = *(const u64*)&s_w[4][k * 32 + lane];
            float ek[4], sk[4];
            ek[0] = __shfl_sync(0xffffffffu, e0, k);
            ek[1] = __shfl_sync(0xffffffffu, e1, k);
            ek[2] = __shfl_sync(0xffffffffu, e2, k);
            ek[3] = __shfl_sync(0xffffffffu, e3, k);
            sk[0] = __shfl_sync(0xffffffffu, r0, k);
            sk[1] = __shfl_sync(0xffffffffu, r1, k);
            sk[2] = __shfl_sync(0xffffffffu, r2, k);
            sk[3] = __shfl_sync(0xffffffffu, r3, k);
#pragma unroll
            for (int i = 0; i < 4; i++) {
                u64 ekk = pack2(ek[i], ek[i]);
                u64 skk = pack2(sk[i], sk[i]);
                A[i] = fma2(w0, ekk, A[i]);
                B[i] = fma2(w1, ekk, B[i]);
                C[i] = fma2(w2, skk, C[i]);
                M[i] = fma2(w3, ekk, M[i]);
                D[i] = fma2(w4, skk, D[i]);
            }
        }

#pragma unroll
        for (int i = 0; i < 4; i++) {
            int n = base + i;
            float lo, hi;
            unpack2(A[i], lo, hi);
            g_tailproj[n * 64 + lane]      = lo;
            g_tailproj[n * 64 + 32 + lane] = hi;
            unpack2(B[i], lo, hi);
            g_headrec[n * 128 + lane]      = lo;
            g_headrec[n * 128 + 32 + lane] = hi;
            unpack2(M[i], lo, hi);
            g_headrec[n * 128 + 64 + lane] = lo;
            g_headrec[n * 128 + 96 + lane] = hi;
            unpack2(C[i], lo, hi);
            g_self[n * 128 + lane]         = lo;
            g_self[n * 128 + 32 + lane]    = hi;
            unpack2(D[i], lo, hi);
            g_self[n * 128 + 64 + lane]    = lo;
            g_self[n * 128 + 96 + lane]    = hi;
        }
    }
}

// ---------------------------------------------------------------------------
// Run-combining edge pass over tail-sorted edges. Each 16-lane group owns 4
// consecutive sorted edges; accumulates in registers while tail unchanged,
// flushes RED on tail change. Cross-sub combine at the end.
__global__ void __launch_bounds__(256) edge_kernel(const float* __restrict__ attn_vec) {
    int lane = threadIdx.x & 31;
    int t    = lane & 15;
    int sub  = lane >> 4;
    unsigned pmask = 3u << (lane & 30);
    int gw   = (blockIdx.x * blockDim.x + threadIdx.x) >> 5;
    int base = gw * 8 + sub * 4;             // N_EDGE % 8 == 0: always in range

    float4 v = *(const float4*)(&attn_vec[4 * t]);

    int   cur = -1;
    float4 at = make_float4(0.f, 0.f, 0.f, 0.f);
    float ax = 0, ay = 0, az = 0, aw = 0, den = 0;

#pragma unroll
    for (int i = 0; i < 4; i++) {
        int2 er = g_sorted[base + i];
        int hn = er.x & 0x1FFFF;
        int r  = er.x >> 17;
        int tn = er.y;

        if (tn != cur) {                      // uniform within the 16-lane group
            if (cur >= 0) {
                float* dst = &g_acc[cur * 64 + 4 * t];
                asm volatile("red.global.add.v4.f32 [%0], {%1,%2,%3,%4};"
                             :: "l"(dst), "f"(ax), "f"(ay), "f"(az), "f"(aw) : "memory");
                if (!(t & 1)) atomicAdd(&g_sum[cur * 8 + (t >> 1)], den);
            }
            cur = tn;
            ax = ay = az = aw = den = 0.f;
            at = *(const float4*)(&g_tailproj[tn * 64 + 4 * t]);
        }

        float4 ah  = *(const float4*)(&g_headrec[hn * 128 + 4 * t]);
        float4 mh  = *(const float4*)(&g_headrec[hn * 128 + 64 + 4 * t]);
        float4 arv = *(const float4*)(&g_arel[r * 64 + 4 * t]);
        float4 mrv = *(const float4*)(&g_mrel[r * 64 + 4 * t]);

        float p0 = at.x + ah.x + arv.x; p0 = fmaxf(p0, 0.2f * p0);
        float p1 = at.y + ah.y + arv.y; p1 = fmaxf(p1, 0.2f * p1);
        float p2 = at.z + ah.z + arv.z; p2 = fmaxf(p2, 0.2f * p2);
        float p3 = at.w + ah.w + arv.w; p3 = fmaxf(p3, 0.2f * p3);
        float s = p0 * v.x + p1 * v.y + p2 * v.z + p3 * v.w;
        s += __shfl_xor_sync(pmask, s, 1);
        float ex = __expf(s);                 // logits O(1): max-pass skip safe

        ax = fmaf(ex, mh.x + mrv.x, ax);
        ay = fmaf(ex, mh.y + mrv.y, ay);
        az = fmaf(ex, mh.z + mrv.z, az);
        aw = fmaf(ex, mh.w + mrv.w, aw);
        den += ex;
    }

    // final flush, combining the two sub-halves when they share a tail
    int other = __shfl_xor_sync(0xffffffffu, cur, 16);
    if (other == cur) {
        ax  += __shfl_xor_sync(0xffffffffu, ax, 16);
        ay  += __shfl_xor_sync(0xffffffffu, ay, 16);
        az  += __shfl_xor_sync(0xffffffffu, az, 16);
        aw  += __shfl_xor_sync(0xffffffffu, aw, 16);
        den += __shfl_xor_sync(0xffffffffu, den, 16);
        if (sub == 0) {
            float* dst = &g_acc[cur * 64 + 4 * t];
            asm volatile("red.global.add.v4.f32 [%0], {%1,%2,%3,%4};"
                         :: "l"(dst), "f"(ax), "f"(ay), "f"(az), "f"(aw) : "memory");
            if (!(t & 1)) atomicAdd(&g_sum[cur * 8 + (t >> 1)], den);
        }
    } else {
        float* dst = &g_acc[cur * 64 + 4 * t];
        asm volatile("red.global.add.v4.f32 [%0], {%1,%2,%3,%4};"
                     :: "l"(dst), "f"(ax), "f"(ay), "f"(az), "f"(aw) : "memory");
        if (!(t & 1)) atomicAdd(&g_sum[cur * 8 + (t >> 1)], den);
    }
}

// ---------------------------------------------------------------------------
// Self-loop edge + normalize + bias: 16 lanes per node, 2 nodes per warp.
__global__ void final_kernel(const float* __restrict__ attn_vec,
                             const float* __restrict__ aggr_b,
                             float* __restrict__ out) {
    int lane = threadIdx.x & 31;
    int t    = lane & 15;
    int sub  = lane >> 4;
    unsigned pmask = 3u << (lane & 30);
    int gw = (blockIdx.x * blockDim.x + threadIdx.x) >> 5;
    int n  = gw * 2 + sub;                   // N_ENT % 2 == 0: exact
    if (n >= N_ENT) return;

    float4 v  = *(const float4*)(&attn_vec[4 * t]);
    float4 at = *(const float4*)(&g_tailproj[n * 64 + 4 * t]);
    float4 ah = *(const float4*)(&g_headrec[n * 128 + 4 * t]);
    float4 mh = *(const float4*)(&g_headrec[n * 128 + 64 + 4 * t]);
    float4 ar = *(const float4*)(&g_self[n * 128 + 4 * t]);
    float4 mr = *(const float4*)(&g_self[n * 128 + 64 + 4 * t]);

    float p0 = at.x + ah.x + ar.x; p0 = fmaxf(p0, 0.2f * p0);
    float p1 = at.y + ah.y + ar.y; p1 = fmaxf(p1, 0.2f * p1);
    float p2 = at.z + ah.z + ar.z; p2 = fmaxf(p2, 0.2f * p2);
    float p3 = at.w + ah.w + ar.w; p3 = fmaxf(p3, 0.2f * p3);
    float s = p0 * v.x + p1 * v.y + p2 * v.z + p3 * v.w;
    s += __shfl_xor_sync(pmask, s, 1);
    float ex = __expf(s);

    float4 acc = *(const float4*)(&g_acc[n * 64 + 4 * t]);
    float den  = g_sum[n * 8 + (t >> 1)];
    float inv  = 1.f / (den + ex + 1e-16f);
    float4 b   = *(const float4*)(&aggr_b[4 * t]);

    float4 o;
    o.x = fmaf(fmaf(ex, mh.x + mr.x, acc.x), inv, b.x);
    o.y = fmaf(fmaf(ex, mh.y + mr.y, acc.y), inv, b.y);
    o.z = fmaf(fmaf(ex, mh.z + mr.z, acc.z), inv, b.z);
    o.w = fmaf(fmaf(ex, mh.w + mr.w, acc.w), inv, b.w);
    *(float4*)(&out[n * 64 + 4 * t]) = o;
}

// ---------------------------------------------------------------------------
extern "C" void kernel_launch(void* const* d_in, const int* in_sizes, int n_in,
                              void* d_out, int out_size) {
    const float* emb_ent  = (const float*)d_in[0];
    const float* emb_rel  = (const float*)d_in[1];
    const float* attn_W   = (const float*)d_in[2];
    const float* attn_b   = (const float*)d_in[3];
    const float* attn_vec = (const float*)d_in[4];
    const float* aggr_W   = (const float*)d_in[5];
    const float* aggr_b   = (const float*)d_in[6];
    const int*   head     = (const int*)d_in[7];
    const int*   tail     = (const int*)d_in[8];
    const int*   rel      = (const int*)d_in[9];
    float*       out      = (float*)d_out;

    void *p_hist, *p_sum, *p_acc;
    cudaGetSymbolAddress(&p_hist, g_hist);
    cudaGetSymbolAddress(&p_sum,  g_sum);
    cudaGetSymbolAddress(&p_acc,  g_acc);
    cudaMemsetAsync(p_hist, 0, sizeof(int)   * N_ENT * 64);
    cudaMemsetAsync(p_sum,  0, sizeof(float) * N_ENT * 8);
    cudaMemsetAsync(p_acc,  0, sizeof(float) * N_ENT * 64);

    rel_tables_kernel<<<1, 64>>>(emb_rel, attn_W, attn_b, aggr_W);
    hist_kernel<<<(N_EDGE + 255) / 256, 256>>>(tail, rel);
    selfrel_kernel<<<(N_ENT + 7) / 8, 256>>>(emb_rel);
    scan_kernel<<<1, 1024>>>();
    scatter_kernel<<<(N_EDGE + 255) / 256, 256>>>(head, tail, rel);
    node_proj_kernel<<<740, 256>>>(emb_ent, attn_W, attn_b, aggr_W);
    edge_kernel<<<N_EDGE / 8 / 8, 256>>>(attn_vec);   // 8 edges/warp, 8 warps/blk
    final_kernel<<<(N_ENT / 2 + 7) / 8, 256>>>(attn_vec, aggr_b, out);
}

// round 7
// speedup vs baseline: 1.3671x; 1.3671x over previous
#include <cuda_runtime.h>

#define N_ENT  100000
#define N_EDGE 1600000
#define N_REL  64
#define NB_SCAN ((N_ENT + 255) / 256)   // 391

// Scratch (allocation-free rule: __device__ globals)
static __device__ float g_tailproj[N_ENT * 64];    // W_t · emb[n]
static __device__ float g_headrec [N_ENT * 128];   // [W_h·emb | M_h·emb]
static __device__ float g_self    [N_ENT * 128];   // [W_r·self_rel + b | M_r·self_rel]
static __device__ float g_selfrel [N_ENT * 32];    // mean incoming rel embedding
static __device__ float g_arel    [N_REL * 64];    // W_r·emb_rel[r] + attn_b
static __device__ float g_mrel    [N_REL * 64];    // M_r·emb_rel[r]
static __device__ int   g_hist    [N_ENT * 64];    // per-node relation histogram
static __device__ int   g_deg     [N_ENT];         // in-degree (excl. self)
static __device__ int   g_off     [N_ENT + 1];     // CSR offsets
static __device__ int   g_cursor  [N_ENT];         // scatter cursors
static __device__ int   g_bsum    [NB_SCAN];       // scan block sums
static __device__ int   g_boff    [NB_SCAN];       // scan block offsets
static __device__ int2  g_sorted  [N_EDGE];        // (head | rel<<17, tail) by tail
static __device__ float g_sum     [N_ENT * 8];     // softmax denominators (real edges)
static __device__ float g_acc     [N_ENT * 64];    // unnormalized accum (real edges)

typedef unsigned long long u64;

__device__ __forceinline__ u64 pack2(float lo, float hi) {
    u64 r;
    asm("mov.b64 %0, {%1, %2};" : "=l"(r) : "f"(lo), "f"(hi));
    return r;
}
__device__ __forceinline__ void unpack2(u64 v, float& lo, float& hi) {
    asm("mov.b64 {%0, %1}, %2;" : "=f"(lo), "=f"(hi) : "l"(v));
}
__device__ __forceinline__ u64 fma2(u64 a, u64 b, u64 c) {
    u64 d;
    asm("fma.rn.f32x2 %0, %1, %2, %3;" : "=l"(d) : "l"(a), "l"(b), "l"(c));
    return d;
}

// ---------------------------------------------------------------------------
__global__ void rel_tables_kernel(const float* __restrict__ emb_rel,
                                  const float* __restrict__ attn_W,
                                  const float* __restrict__ attn_b,
                                  const float* __restrict__ aggr_W) {
    int r = threadIdx.x;
    if (r >= N_REL) return;
    float ev[32];
#pragma unroll
    for (int k = 0; k < 32; k++) ev[k] = emb_rel[r * 32 + k];
    for (int o = 0; o < 64; o++) {
        float a = attn_b[o], m = 0.f;
#pragma unroll
        for (int k = 0; k < 32; k++) {
            a = fmaf(attn_W[o * 96 + 64 + k], ev[k], a);
            m = fmaf(aggr_W[o * 64 + 32 + k], ev[k], m);
        }
        g_arel[r * 64 + o] = a;
        g_mrel[r * 64 + o] = m;
    }
}

// ---------------------------------------------------------------------------
__global__ void hist_kernel(const int* __restrict__ tail,
                            const int* __restrict__ rel) {
    int e = blockIdx.x * blockDim.x + threadIdx.x;
    if (e < N_EDGE) atomicAdd(&g_hist[tail[e] * 64 + rel[e]], 1);
}

// ---------------------------------------------------------------------------
// Mean incoming rel embedding per node (32-dim) + degree: one warp per node.
__global__ void selfrel_kernel(const float* __restrict__ emb_rel) {
    __shared__ float s_rel[N_REL * 32];   // 8KB
    for (int i = threadIdx.x; i < N_REL * 32; i += blockDim.x)
        s_rel[i] = emb_rel[i];
    __syncthreads();
    int lane = threadIdx.x & 31;
    int n = blockIdx.x * (blockDim.x >> 5) + (threadIdx.x >> 5);
    if (n >= N_ENT) return;
    int h0 = g_hist[n * 64 + lane];
    int h1 = g_hist[n * 64 + 32 + lane];
    unsigned tot = __reduce_add_sync(0xffffffffu, (unsigned)(h0 + h1));
    if (lane == 0) g_deg[n] = (int)tot;
    float inv = 1.f / (float)tot;
    float acc = 0.f;
#pragma unroll
    for (int r = 0; r < 64; r++) {
        int hr = (r < 32) ? __shfl_sync(0xffffffffu, h0, r)
                          : __shfl_sync(0xffffffffu, h1, r - 32);
        if (hr) acc = fmaf((float)hr, s_rel[r * 32 + lane], acc);
    }
    g_selfrel[n * 32 + lane] = acc * inv;
}

// ---------------------------------------------------------------------------
// 3-phase multi-block exclusive scan over degrees
__global__ void scanA_kernel() {
    __shared__ int s[256];
    int n = blockIdx.x * 256 + threadIdx.x;
    s[threadIdx.x] = (n < N_ENT) ? g_deg[n] : 0;
    __syncthreads();
    for (int o = 128; o > 0; o >>= 1) {
        if (threadIdx.x < o) s[threadIdx.x] += s[threadIdx.x + o];
        __syncthreads();
    }
    if (threadIdx.x == 0) g_bsum[blockIdx.x] = s[0];
}
__global__ void scanB_kernel() {
    __shared__ int s[512];
    int tid = threadIdx.x;
    s[tid] = (tid < NB_SCAN) ? g_bsum[tid] : 0;
    __syncthreads();
    for (int d = 1; d < 512; d <<= 1) {
        int v = (tid >= d) ? s[tid - d] : 0;
        __syncthreads();
        s[tid] += v;
        __syncthreads();
    }
    if (tid < NB_SCAN) g_boff[tid] = tid ? s[tid - 1] : 0;
    if (tid == 511) g_off[N_ENT] = s[NB_SCAN - 1];
}
__global__ void scanC_kernel() {
    __shared__ int s[256];
    int n = blockIdx.x * 256 + threadIdx.x;
    int d = (n < N_ENT) ? g_deg[n] : 0;
    s[threadIdx.x] = d;
    __syncthreads();
    for (int o = 1; o < 256; o <<= 1) {
        int v = (threadIdx.x >= o) ? s[threadIdx.x - o] : 0;
        __syncthreads();
        s[threadIdx.x] += v;
        __syncthreads();
    }
    if (n < N_ENT) {
        int off = g_boff[blockIdx.x] + s[threadIdx.x] - d;   // exclusive
        g_off[n]    = off;
        g_cursor[n] = off;
    }
}

// ---------------------------------------------------------------------------
__global__ void scatter_kernel(const int* __restrict__ head,
                               const int* __restrict__ tail,
                               const int* __restrict__ rel) {
    int e = blockIdx.x * blockDim.x + threadIdx.x;
    if (e >= N_EDGE) return;
    int tn = tail[e];
    int pos = atomicAdd(&g_cursor[tn], 1);
    g_sorted[pos] = make_int2(head[e] | (rel[e] << 17), tn);
}

// ---------------------------------------------------------------------------
// Per-node projections (5 GEMVs fused): 4 nodes per warp per k-step, weights
// packed as (o=lane, o=lane+32) float2 pairs -> LDS.64 + fma.rn.f32x2.
__global__ void __launch_bounds__(256) node_proj_kernel(
        const float* __restrict__ emb_ent,
        const float* __restrict__ attn_W,
        const float* __restrict__ attn_b,
        const float* __restrict__ aggr_W) {
    __shared__ float2 s_w[5][32 * 32];
    for (int i = threadIdx.x; i < 1024; i += blockDim.x) {
        int k = i >> 5, l = i & 31;
        s_w[0][i] = make_float2(attn_W[l * 96 + k],      attn_W[(l + 32) * 96 + k]);
        s_w[1][i] = make_float2(attn_W[l * 96 + 32 + k], attn_W[(l + 32) * 96 + 32 + k]);
        s_w[2][i] = make_float2(attn_W[l * 96 + 64 + k], attn_W[(l + 32) * 96 + 64 + k]);
        s_w[3][i] = make_float2(aggr_W[l * 64 + k],      aggr_W[(l + 32) * 64 + k]);
        s_w[4][i] = make_float2(aggr_W[l * 64 + 32 + k], aggr_W[(l + 32) * 64 + 32 + k]);
    }
    __syncthreads();

    int lane = threadIdx.x & 31;
    int gw   = blockIdx.x * (blockDim.x >> 5) + (threadIdx.x >> 5);
    int GW   = gridDim.x * (blockDim.x >> 5);
    u64 bias = pack2(attn_b[lane], attn_b[32 + lane]);

    for (int base = gw * 4; base < N_ENT; base += GW * 4) {   // N_ENT % 4 == 0
        float e0 = emb_ent[(base + 0) * 32 + lane];
        float e1 = emb_ent[(base + 1) * 32 + lane];
        float e2 = emb_ent[(base + 2) * 32 + lane];
        float e3 = emb_ent[(base + 3) * 32 + lane];
        float r0 = g_selfrel[(base + 0) * 32 + lane];
        float r1 = g_selfrel[(base + 1) * 32 + lane];
        float r2 = g_selfrel[(base + 2) * 32 + lane];
        float r3 = g_selfrel[(base + 3) * 32 + lane];

        u64 A[4], B[4], C[4], M[4], D[4];
#pragma unroll
        for (int i = 0; i < 4; i++) { A[i] = 0; B[i] = 0; C[i] = bias; M[i] = 0; D[i] = 0; }

#pragma unroll
        for (int k = 0; k < 32; k++) {
            u64 w0 = *(const u64*)&s_w[0][k * 32 + lane];
            u64 w1 = *(const u64*)&s_w[1][k * 32 + lane];
            u64 w2 = *(const u64*)&s_w[2][k * 32 + lane];
            u64 w3 = *(const u64*)&s_w[3][k * 32 + lane];
            u64 w4 = *(const u64*)&s_w[4][k * 32 + lane];
            float ek[4], sk[4];
            ek[0] = __shfl_sync(0xffffffffu, e0, k);
            ek[1] = __shfl_sync(0xffffffffu, e1, k);
            ek[2] = __shfl_sync(0xffffffffu, e2, k);
            ek[3] = __shfl_sync(0xffffffffu, e3, k);
            sk[0] = __shfl_sync(0xffffffffu, r0, k);
            sk[1] = __shfl_sync(0xffffffffu, r1, k);
            sk[2] = __shfl_sync(0xffffffffu, r2, k);
            sk[3] = __shfl_sync(0xffffffffu, r3, k);
#pragma unroll
            for (int i = 0; i < 4; i++) {
                u64 ekk = pack2(ek[i], ek[i]);
                u64 skk = pack2(sk[i], sk[i]);
                A[i] = fma2(w0, ekk, A[i]);
                B[i] = fma2(w1, ekk, B[i]);
                C[i] = fma2(w2, skk, C[i]);
                M[i] = fma2(w3, ekk, M[i]);
                D[i] = fma2(w4, skk, D[i]);
            }
        }

#pragma unroll
        for (int i = 0; i < 4; i++) {
            int n = base + i;
            float lo, hi;
            unpack2(A[i], lo, hi);
            g_tailproj[n * 64 + lane]      = lo;
            g_tailproj[n * 64 + 32 + lane] = hi;
            unpack2(B[i], lo, hi);
            g_headrec[n * 128 + lane]      = lo;
            g_headrec[n * 128 + 32 + lane] = hi;
            unpack2(M[i], lo, hi);
            g_headrec[n * 128 + 64 + lane] = lo;
            g_headrec[n * 128 + 96 + lane] = hi;
            unpack2(C[i], lo, hi);
            g_self[n * 128 + lane]         = lo;
            g_self[n * 128 + 32 + lane]    = hi;
            unpack2(D[i], lo, hi);
            g_self[n * 128 + 64 + lane]    = lo;
            g_self[n * 128 + 96 + lane]    = hi;
        }
    }
}

// ---------------------------------------------------------------------------
// Run-combining edge pass over tail-sorted edges: 8 consecutive edges per
// 16-lane group; register accumulation while tail unchanged, RED on change.
__global__ void __launch_bounds__(256) edge_kernel(const float* __restrict__ attn_vec) {
    int lane = threadIdx.x & 31;
    int t    = lane & 15;
    int sub  = lane >> 4;
    unsigned pmask = 3u << (lane & 30);
    int gw   = (blockIdx.x * blockDim.x + threadIdx.x) >> 5;
    int base = gw * 16 + sub * 8;            // N_EDGE % 16 == 0: always in range

    float4 v = *(const float4*)(&attn_vec[4 * t]);

    int   cur = -1;
    float4 at = make_float4(0.f, 0.f, 0.f, 0.f);
    float ax = 0, ay = 0, az = 0, aw = 0, den = 0;

#pragma unroll
    for (int i = 0; i < 8; i++) {
        int2 er = g_sorted[base + i];
        int hn = er.x & 0x1FFFF;
        int r  = er.x >> 17;
        int tn = er.y;

        if (tn != cur) {                      // uniform within the 16-lane group
            if (cur >= 0) {
                float* dst = &g_acc[cur * 64 + 4 * t];
                asm volatile("red.global.add.v4.f32 [%0], {%1,%2,%3,%4};"
                             :: "l"(dst), "f"(ax), "f"(ay), "f"(az), "f"(aw) : "memory");
                if (!(t & 1)) atomicAdd(&g_sum[cur * 8 + (t >> 1)], den);
            }
            cur = tn;
            ax = ay = az = aw = den = 0.f;
            at = *(const float4*)(&g_tailproj[tn * 64 + 4 * t]);
        }

        float4 ah  = *(const float4*)(&g_headrec[hn * 128 + 4 * t]);
        float4 mh  = *(const float4*)(&g_headrec[hn * 128 + 64 + 4 * t]);
        float4 arv = *(const float4*)(&g_arel[r * 64 + 4 * t]);
        float4 mrv = *(const float4*)(&g_mrel[r * 64 + 4 * t]);

        float p0 = at.x + ah.x + arv.x; p0 = fmaxf(p0, 0.2f * p0);
        float p1 = at.y + ah.y + arv.y; p1 = fmaxf(p1, 0.2f * p1);
        float p2 = at.z + ah.z + arv.z; p2 = fmaxf(p2, 0.2f * p2);
        float p3 = at.w + ah.w + arv.w; p3 = fmaxf(p3, 0.2f * p3);
        float s = p0 * v.x + p1 * v.y + p2 * v.z + p3 * v.w;
        s += __shfl_xor_sync(pmask, s, 1);
        float ex = __expf(s);                 // logits O(1): max-pass skip safe

        ax = fmaf(ex, mh.x + mrv.x, ax);
        ay = fmaf(ex, mh.y + mrv.y, ay);
        az = fmaf(ex, mh.z + mrv.z, az);
        aw = fmaf(ex, mh.w + mrv.w, aw);
        den += ex;
    }

    // final flush, combining the two sub-halves when they share a tail
    int other = __shfl_xor_sync(0xffffffffu, cur, 16);
    if (other == cur) {
        ax  += __shfl_xor_sync(0xffffffffu, ax, 16);
        ay  += __shfl_xor_sync(0xffffffffu, ay, 16);
        az  += __shfl_xor_sync(0xffffffffu, az, 16);
        aw  += __shfl_xor_sync(0xffffffffu, aw, 16);
        den += __shfl_xor_sync(0xffffffffu, den, 16);
        if (sub == 0) {
            float* dst = &g_acc[cur * 64 + 4 * t];
            asm volatile("red.global.add.v4.f32 [%0], {%1,%2,%3,%4};"
                         :: "l"(dst), "f"(ax), "f"(ay), "f"(az), "f"(aw) : "memory");
            if (!(t & 1)) atomicAdd(&g_sum[cur * 8 + (t >> 1)], den);
        }
    } else {
        float* dst = &g_acc[cur * 64 + 4 * t];
        asm volatile("red.global.add.v4.f32 [%0], {%1,%2,%3,%4};"
                     :: "l"(dst), "f"(ax), "f"(ay), "f"(az), "f"(aw) : "memory");
        if (!(t & 1)) atomicAdd(&g_sum[cur * 8 + (t >> 1)], den);
    }
}

// ---------------------------------------------------------------------------
// Self-loop edge + normalize + bias: 16 lanes per node, 2 nodes per warp.
__global__ void final_kernel(const float* __restrict__ attn_vec,
                             const float* __restrict__ aggr_b,
                             float* __restrict__ out) {
    int lane = threadIdx.x & 31;
    int t    = lane & 15;
    int sub  = lane >> 4;
    unsigned pmask = 3u << (lane & 30);
    int gw = (blockIdx.x * blockDim.x + threadIdx.x) >> 5;
    int n  = gw * 2 + sub;                   // N_ENT % 2 == 0: exact
    if (n >= N_ENT) return;

    float4 v  = *(const float4*)(&attn_vec[4 * t]);
    float4 at = *(const float4*)(&g_tailproj[n * 64 + 4 * t]);
    float4 ah = *(const float4*)(&g_headrec[n * 128 + 4 * t]);
    float4 mh = *(const float4*)(&g_headrec[n * 128 + 64 + 4 * t]);
    float4 ar = *(const float4*)(&g_self[n * 128 + 4 * t]);
    float4 mr = *(const float4*)(&g_self[n * 128 + 64 + 4 * t]);

    float p0 = at.x + ah.x + ar.x; p0 = fmaxf(p0, 0.2f * p0);
    float p1 = at.y + ah.y + ar.y; p1 = fmaxf(p1, 0.2f * p1);
    float p2 = at.z + ah.z + ar.z; p2 = fmaxf(p2, 0.2f * p2);
    float p3 = at.w + ah.w + ar.w; p3 = fmaxf(p3, 0.2f * p3);
    float s = p0 * v.x + p1 * v.y + p2 * v.z + p3 * v.w;
    s += __shfl_xor_sync(pmask, s, 1);
    float ex = __expf(s);

    float4 acc = *(const float4*)(&g_acc[n * 64 + 4 * t]);
    float den  = g_sum[n * 8 + (t >> 1)];
    float inv  = 1.f / (den + ex + 1e-16f);
    float4 b   = *(const float4*)(&aggr_b[4 * t]);

    float4 o;
    o.x = fmaf(fmaf(ex, mh.x + mr.x, acc.x), inv, b.x);
    o.y = fmaf(fmaf(ex, mh.y + mr.y, acc.y), inv, b.y);
    o.z = fmaf(fmaf(ex, mh.z + mr.z, acc.z), inv, b.z);
    o.w = fmaf(fmaf(ex, mh.w + mr.w, acc.w), inv, b.w);
    *(float4*)(&out[n * 64 + 4 * t]) = o;
}

// ---------------------------------------------------------------------------
extern "C" void kernel_launch(void* const* d_in, const int* in_sizes, int n_in,
                              void* d_out, int out_size) {
    const float* emb_ent  = (const float*)d_in[0];
    const float* emb_rel  = (const float*)d_in[1];
    const float* attn_W   = (const float*)d_in[2];
    const float* attn_b   = (const float*)d_in[3];
    const float* attn_vec = (const float*)d_in[4];
    const float* aggr_W   = (const float*)d_in[5];
    const float* aggr_b   = (const float*)d_in[6];
    const int*   head     = (const int*)d_in[7];
    const int*   tail     = (const int*)d_in[8];
    const int*   rel      = (const int*)d_in[9];
    float*       out      = (float*)d_out;

    void *p_hist, *p_sum, *p_acc;
    cudaGetSymbolAddress(&p_hist, g_hist);
    cudaGetSymbolAddress(&p_sum,  g_sum);
    cudaGetSymbolAddress(&p_acc,  g_acc);
    cudaMemsetAsync(p_hist, 0, sizeof(int)   * N_ENT * 64);
    cudaMemsetAsync(p_sum,  0, sizeof(float) * N_ENT * 8);
    cudaMemsetAsync(p_acc,  0, sizeof(float) * N_ENT * 64);

    rel_tables_kernel<<<1, 64>>>(emb_rel, attn_W, attn_b, aggr_W);
    hist_kernel<<<(N_EDGE + 255) / 256, 256>>>(tail, rel);
    selfrel_kernel<<<(N_ENT + 7) / 8, 256>>>(emb_rel);
    scanA_kernel<<<NB_SCAN, 256>>>();
    scanB_kernel<<<1, 512>>>();
    scanC_kernel<<<NB_SCAN, 256>>>();
    scatter_kernel<<<(N_EDGE + 255) / 256, 256>>>(head, tail, rel);
    node_proj_kernel<<<740, 256>>>(emb_ent, attn_W, attn_b, aggr_W);
    edge_kernel<<<N_EDGE / 16 / 8, 256>>>(attn_vec);   // 16 edges/warp
    final_kernel<<<(N_ENT / 2 + 7) / 8, 256>>>(attn_vec, aggr_b, out);
}